// round 4
// baseline (speedup 1.0000x reference)
#include <cuda_runtime.h>
#include <cuda_bf16.h>
#include <cstdint>

// Problem constants
#define BB   32
#define CC   64
#define HH   128
#define WW   128
#define OUTC 64
#define KK   3
#define HID  128
#define WSZ  (OUTC * CC * KK * KK)   // 36864 per-sample weight elements

typedef unsigned long long ull;

// Scratch (static device globals — no allocation allowed)
__device__ float g_stats[BB * CC];             // [b][c]
__device__ float g_hidden[BB * HID];           // [b][h]
__device__ float g_weight[(size_t)BB * WSZ];   // permuted: [b][c][k][o]  (k = kh*3+kw, o innermost)

// ---------------------------------------------------------------------------
// packed f32x2 helpers (Blackwell sm_103a)
// ---------------------------------------------------------------------------
__device__ __forceinline__ void fma2(ull& d, ull a, ull b) {
    asm("fma.rn.f32x2 %0, %1, %2, %0;" : "+l"(d) : "l"(a), "l"(b));
}
__device__ __forceinline__ ull dup2(float v) {
    ull r;
    asm("mov.b64 %0, {%1, %1};" : "=l"(r) : "f"(v));
    return r;
}
__device__ __forceinline__ void unpack2(float& lo, float& hi, ull v) {
    asm("mov.b64 {%0, %1}, %2;" : "=f"(lo), "=f"(hi) : "l"(v));
}

// ---------------------------------------------------------------------------
// Kernel 1: per-(b,c) spatial mean.  grid=2048 blocks, 256 threads.
// ---------------------------------------------------------------------------
__global__ void stats_kernel(const float* __restrict__ x) {
    int bc = blockIdx.x;  // 0..2047
    const float4* xv = reinterpret_cast<const float4*>(x + (size_t)bc * (HH * WW));
    float s = 0.f;
#pragma unroll
    for (int i = 0; i < 16; ++i) {
        float4 v = xv[threadIdx.x + i * 256];
        s += (v.x + v.y) + (v.z + v.w);
    }
#pragma unroll
    for (int off = 16; off; off >>= 1) s += __shfl_xor_sync(0xffffffffu, s, off);
    __shared__ float red[8];
    if ((threadIdx.x & 31) == 0) red[threadIdx.x >> 5] = s;
    __syncthreads();
    if (threadIdx.x < 8) {
        float t = red[threadIdx.x];
#pragma unroll
        for (int off = 4; off; off >>= 1) t += __shfl_xor_sync(0xffu, t, off);
        if (threadIdx.x == 0) g_stats[bc] = t * (1.0f / (HH * WW));
    }
}

// ---------------------------------------------------------------------------
// Kernel 2: hidden = relu(stats @ W1 + b1).  grid=32, block=128.
// ---------------------------------------------------------------------------
__global__ void hidden_kernel(const float* __restrict__ W1, const float* __restrict__ b1) {
    int b = blockIdx.x;
    __shared__ float s[CC];
    if (threadIdx.x < CC) s[threadIdx.x] = g_stats[b * CC + threadIdx.x];
    __syncthreads();
    int h = threadIdx.x;
    float acc = b1[h];
#pragma unroll 8
    for (int c = 0; c < CC; ++c) acc += s[c] * W1[c * HID + h];
    g_hidden[b * HID + h] = fmaxf(acc, 0.0f);
}

// ---------------------------------------------------------------------------
// Kernel 3: weight = hidden @ W2 + b2, stored permuted [b][c][k][o].
// W2 column j corresponds to: j = o*(CC*9) + c*9 + k
// ---------------------------------------------------------------------------
__global__ void wgen_kernel(const float* __restrict__ W2, const float* __restrict__ b2) {
    __shared__ float sh[8][HID];
    int b0 = blockIdx.y * 8;
    for (int i = threadIdx.x; i < 8 * HID; i += 256)
        sh[i >> 7][i & 127] = g_hidden[(b0 + (i >> 7)) * HID + (i & 127)];
    __syncthreads();

    int j0 = blockIdx.x * 1024 + threadIdx.x * 4;
    float4 acc[8];
#pragma unroll
    for (int bb = 0; bb < 8; ++bb) acc[bb] = make_float4(0.f, 0.f, 0.f, 0.f);

    for (int k = 0; k < HID; ++k) {
        float4 wv = *reinterpret_cast<const float4*>(&W2[(size_t)k * WSZ + j0]);
#pragma unroll
        for (int bb = 0; bb < 8; ++bb) {
            float hv = sh[bb][k];
            acc[bb].x = fmaf(hv, wv.x, acc[bb].x);
            acc[bb].y = fmaf(hv, wv.y, acc[bb].y);
            acc[bb].z = fmaf(hv, wv.z, acc[bb].z);
            acc[bb].w = fmaf(hv, wv.w, acc[bb].w);
        }
    }
    float4 bias = *reinterpret_cast<const float4*>(&b2[j0]);
#pragma unroll
    for (int bb = 0; bb < 8; ++bb) {
        float vals[4] = {acc[bb].x + bias.x, acc[bb].y + bias.y,
                         acc[bb].z + bias.z, acc[bb].w + bias.w};
#pragma unroll
        for (int q = 0; q < 4; ++q) {
            int j = j0 + q;
            int o = j / (CC * KK * KK);
            int rem = j % (CC * KK * KK);
            int c = rem / (KK * KK);
            int k = rem % (KK * KK);
            // permuted layout [b][c][k][o]
            g_weight[(((size_t)(b0 + bb) * CC + c) * (KK * KK) + k) * OUTC + o] = vals[q];
        }
    }
}

// ---------------------------------------------------------------------------
// Kernel 4: grouped conv using packed fp32x2 FMA (FFMA2).
// grid = (8, 8, 32): (w-tile, h-tile, b).  block = 512 threads (16 warps).
// Warp wid: o0 = (wid&7)*8  (8 output channels, 4 packed o-pairs)
//           band = wid>>3   (rows band*8 .. band*8+7)
// Lane tp:  col = tp&15, sub = tp>>4 -> r0 = band*8 + sub*4 (4 rows)
// Thread computes 8 o x 4 rows x 1 col = 32 outputs as 16 f32x2 accumulators
// packed over adjacent output channels.  Weight pairs (w[o][k], w[o+1][k])
// load natively as 8-byte SMEM words ([k][o] layout, o innermost).
// x values are register-duplicated once and reused across all 4 o-pairs.
// ---------------------------------------------------------------------------
__global__ __launch_bounds__(512, 1)
void conv_kernel(const float* __restrict__ x, float* __restrict__ out) {
    __shared__ float sx[18 * 20];        // x tile with halo, row stride 20
    __shared__ float sw2[9 * OUTC];      // weights for current c: [k][o]

    int b  = blockIdx.z;
    int h0 = blockIdx.y * 16;
    int w0 = blockIdx.x * 16;
    int tid = threadIdx.x;
    int tp  = tid & 31;
    int wid = tid >> 5;
    int o0  = (wid & 7) * 8;
    int band = wid >> 3;
    int col = tp & 15;
    int r0  = band * 8 + (tp >> 4) * 4;

    ull acc[4][4];   // [o-pair][row]
#pragma unroll
    for (int op = 0; op < 4; ++op)
#pragma unroll
        for (int r = 0; r < 4; ++r) acc[op][r] = 0ull;

    const float* xb = x + (size_t)b * CC * HH * WW;
    const float* wb = g_weight + (size_t)b * WSZ;

    for (int c = 0; c < CC; ++c) {
        __syncthreads();
        // load 18x18 input tile (with zero halo), row stride 20
        if (tid < 324) {
            int rr = tid / 18, cc2 = tid % 18;
            int gr = h0 + rr - 1, gc = w0 + cc2 - 1;
            float v = 0.f;
            if ((unsigned)gr < (unsigned)HH && (unsigned)gc < (unsigned)WW)
                v = xb[(size_t)c * (HH * WW) + gr * WW + gc];
            sx[rr * 20 + cc2] = v;
        }
        // load 576 weights for this (b,c): layout [k][o]
        {
            int i = tid;
            if (i < 576) sw2[i] = wb[c * (OUTC * 9) + i];
            i += 512;
            if (i < 576) sw2[i] = wb[c * (OUTC * 9) + i];
        }
        __syncthreads();

        // per-thread x registers, duplicated for packed FMA: rows r0..r0+5, 3 cols
        ull xd[6][3];
#pragma unroll
        for (int j = 0; j < 6; ++j)
#pragma unroll
            for (int dc = 0; dc < 3; ++dc)
                xd[j][dc] = dup2(sx[(r0 + j) * 20 + col + dc]);

#pragma unroll
        for (int k = 0; k < 9; ++k) {
            int dr = k / 3, dc = k % 3;
            // 4 weight pairs for this k: o0..o0+7, adjacent-o packed (8B aligned)
            const ull* wq = reinterpret_cast<const ull*>(&sw2[k * OUTC + o0]);
            ull wp0 = wq[0], wp1 = wq[1], wp2 = wq[2], wp3 = wq[3];
#pragma unroll
            for (int r = 0; r < 4; ++r) {
                ull xv = xd[r + dr][dc];
                fma2(acc[0][r], xv, wp0);
                fma2(acc[1][r], xv, wp1);
                fma2(acc[2][r], xv, wp2);
                fma2(acc[3][r], xv, wp3);
            }
        }
    }

    // write out: rows h0+r0..+3, col w0+col, channels o0..o0+7
#pragma unroll
    for (int op = 0; op < 4; ++op) {
        int o = o0 + op * 2;
        float* p0 = out + (((size_t)b * OUTC + o)     * HH + (h0 + r0)) * WW + (w0 + col);
        float* p1 = out + (((size_t)b * OUTC + o + 1) * HH + (h0 + r0)) * WW + (w0 + col);
#pragma unroll
        for (int r = 0; r < 4; ++r) {
            float lo, hi;
            unpack2(lo, hi, acc[op][r]);
            p0[r * WW] = lo;
            p1[r * WW] = hi;
        }
    }
}

// ---------------------------------------------------------------------------
extern "C" void kernel_launch(void* const* d_in, const int* in_sizes, int n_in,
                              void* d_out, int out_size) {
    const float* x  = (const float*)d_in[0];
    const float* W1 = (const float*)d_in[1];
    const float* b1 = (const float*)d_in[2];
    const float* W2 = (const float*)d_in[3];
    const float* b2 = (const float*)d_in[4];
    float* out = (float*)d_out;

    stats_kernel<<<BB * CC, 256>>>(x);
    hidden_kernel<<<BB, HID>>>(W1, b1);
    wgen_kernel<<<dim3(WSZ / 1024, BB / 8), 256>>>(W2, b2);
    conv_kernel<<<dim3(WW / 16, HH / 16, BB), 512>>>(x, out);
}

// round 6
// speedup vs baseline: 3.1098x; 3.1098x over previous
#include <cuda_runtime.h>
#include <cuda_bf16.h>
#include <cstdint>

#define BB   32
#define CC   64
#define HH   128
#define WW   128
#define OUTC 64
#define HID  128

// NHWC planes with halo rows: per (b,h): 130 rows (w=-1..128) x 64 c
#define PROW   64                 // elems per row (128B)
#define PSIZE  (130 * PROW)       // 8320 elems per plane per split
#define PBYTES (PSIZE * 2)        // 16640 B
// Weights per (b, o-half): [9 tap][2 split][64 c][32 o'] = 36864 elems
#define WTILE  (64 * 32)          // 2048 elems per tap-split
#define WSLICE (9 * 2 * WTILE)    // 36864

// ---------------------------------------------------------------------------
// Device scratch (static globals — no allocation allowed)
// ---------------------------------------------------------------------------
__device__ float g_stats[BB * CC];
__device__ float g_hidden[BB * HID];
__device__ __align__(128) uint16_t g_wt[(size_t)BB * 2 * WSLICE];
__device__ __align__(128) uint16_t g_xhi[(size_t)BB * HH * PSIZE];
__device__ __align__(128) uint16_t g_xlo[(size_t)BB * HH * PSIZE];

// ---------------------------------------------------------------------------
// PTX helpers
// ---------------------------------------------------------------------------
__device__ __forceinline__ uint32_t smem_u32(const void* p) {
    uint32_t a;
    asm("{ .reg .u64 t; cvta.to.shared.u64 t, %1; cvt.u32.u64 %0, t; }" : "=r"(a) : "l"(p));
    return a;
}
#define MBAR_INIT(a, n) asm volatile("mbarrier.init.shared.b64 [%0], %1;" :: "r"(a), "r"(n) : "memory")
#define MBAR_EXPECT_TX(a, b) asm volatile("mbarrier.arrive.expect_tx.shared.b64 _, [%0], %1;" :: "r"(a), "r"(b) : "memory")
#define MBAR_WAIT(a, ph) do {                                                         \
    uint32_t _m = (a), _p = (ph), _d;                                                 \
    asm volatile("{\n\t.reg .pred p;\n\t"                                             \
        "mbarrier.try_wait.parity.acquire.cta.shared::cta.b64 p, [%1], %2;\n\t"       \
        "selp.b32 %0, 1, 0, p;\n\t}" : "=r"(_d) : "r"(_m), "r"(_p) : "memory");       \
    if (!_d) {                                                                        \
        asm volatile("{\n\t.reg .pred P1;\n\t"                                        \
            "WL_%=:\n\t"                                                              \
            "mbarrier.try_wait.parity.acquire.cta.shared::cta.b64 P1, [%0], %1, 0x989680;\n\t" \
            "@P1 bra.uni WD_%=;\n\t"                                                  \
            "bra.uni WL_%=;\n\t"                                                      \
            "WD_%=:\n\t}" :: "r"(_m), "r"(_p) : "memory");                            \
    }                                                                                 \
} while (0)
#define BULK_G2S(dst, src, bytes, mbar)                                               \
    asm volatile("cp.async.bulk.shared::cta.global.mbarrier::complete_tx::bytes "      \
                 "[%0], [%1], %2, [%3];"                                               \
                 :: "r"(dst), "l"(src), "r"(bytes), "r"(mbar) : "memory")

__device__ __forceinline__ void ldm_x4(uint32_t* r, uint32_t addr) {
    asm volatile("ldmatrix.sync.aligned.m8n8.x4.shared.b16 {%0,%1,%2,%3}, [%4];"
                 : "=r"(r[0]), "=r"(r[1]), "=r"(r[2]), "=r"(r[3]) : "r"(addr));
}
__device__ __forceinline__ void ldm_x4_t(uint32_t* r, uint32_t addr) {
    asm volatile("ldmatrix.sync.aligned.m8n8.x4.trans.shared.b16 {%0,%1,%2,%3}, [%4];"
                 : "=r"(r[0]), "=r"(r[1]), "=r"(r[2]), "=r"(r[3]) : "r"(addr));
}
__device__ __forceinline__ void mma_bf16(float* d, const uint32_t* a, const uint32_t* b) {
    asm volatile("mma.sync.aligned.m16n8k16.row.col.f32.bf16.bf16.f32 "
                 "{%0,%1,%2,%3}, {%4,%5,%6,%7}, {%8,%9}, {%0,%1,%2,%3};"
                 : "+f"(d[0]), "+f"(d[1]), "+f"(d[2]), "+f"(d[3])
                 : "r"(a[0]), "r"(a[1]), "r"(a[2]), "r"(a[3]), "r"(b[0]), "r"(b[1]));
}

// ---------------------------------------------------------------------------
// Kernel 0: zero stats
// ---------------------------------------------------------------------------
__global__ void zero_stats_kernel() {
    g_stats[blockIdx.x * 256 + threadIdx.x] = 0.f;
}

// ---------------------------------------------------------------------------
// Kernel 1: prep — NCHW fp32 -> halo'd NHWC bf16 hi/lo (chunk-swizzled) + sums
// grid (h=128, b=32), 256 threads.
// Storage row = w+1 (rows 0 and 129 are zero halo). chunk = cblk ^ (row & 7).
// ---------------------------------------------------------------------------
__global__ __launch_bounds__(256) void prep_kernel(const float* __restrict__ x) {
    int h = blockIdx.x, b = blockIdx.y;
    __shared__ float s[CC * 129];
    const float* xb = x + (size_t)b * CC * HH * WW + (size_t)h * WW;
    int t = threadIdx.x;
#pragma unroll
    for (int i = 0; i < 32; ++i) {
        int idx = i * 256 + t;
        int c = idx >> 7, w = idx & 127;
        s[c * 129 + w] = xb[(size_t)c * (HH * WW) + w];
    }
    __syncthreads();
    if (t < CC) {
        float sum = 0.f;
#pragma unroll 8
        for (int w = 0; w < WW; ++w) sum += s[t * 129 + w];
        atomicAdd(&g_stats[b * CC + t], sum);
    }
    int w = t >> 1, half = t & 1;
    __align__(16) uint16_t hbuf[32];
    __align__(16) uint16_t lbuf[32];
#pragma unroll
    for (int e = 0; e < 32; ++e) {
        float v = s[(half * 32 + e) * 129 + w];
        __nv_bfloat16 hi = __float2bfloat16(v);
        float rem = v - __bfloat162float(hi);
        __nv_bfloat16 lo = __float2bfloat16(rem);
        hbuf[e] = *reinterpret_cast<uint16_t*>(&hi);
        lbuf[e] = *reinterpret_cast<uint16_t*>(&lo);
    }
    size_t rowbase = ((size_t)b * HH + h) * PSIZE + (size_t)(w + 1) * PROW;
    uint16_t* dh = g_xhi + rowbase;
    uint16_t* dl = g_xlo + rowbase;
    int ph = (w + 1) & 7;
#pragma unroll
    for (int g = 0; g < 4; ++g) {
        int chunk = (half * 4 + g) ^ ph;
        *reinterpret_cast<uint4*>(dh + chunk * 8) = *reinterpret_cast<const uint4*>(hbuf + g * 8);
        *reinterpret_cast<uint4*>(dl + chunk * 8) = *reinterpret_cast<const uint4*>(lbuf + g * 8);
    }
    // zero halo rows 0 and 129 (hi and lo): 4 regions x 8 chunks of 16B
    if (t < 32) {
        int reg = t >> 3, ch = t & 7;
        uint16_t* base = ((reg & 2) ? g_xlo : g_xhi)
                       + ((size_t)b * HH + h) * PSIZE
                       + ((reg & 1) ? (size_t)129 * PROW : 0) + ch * 8;
        *reinterpret_cast<uint4*>(base) = make_uint4(0u, 0u, 0u, 0u);
    }
}

// ---------------------------------------------------------------------------
// Kernel 2: hidden = relu(mean @ W1 + b1)   (g_stats holds sums)
// ---------------------------------------------------------------------------
__global__ void hidden_kernel(const float* __restrict__ W1, const float* __restrict__ b1) {
    int b = blockIdx.x;
    __shared__ float s[CC];
    if (threadIdx.x < CC) s[threadIdx.x] = g_stats[b * CC + threadIdx.x] * (1.0f / (HH * WW));
    __syncthreads();
    int h = threadIdx.x;
    float acc = b1[h];
#pragma unroll 8
    for (int c = 0; c < CC; ++c) acc += s[c] * W1[c * HID + h];
    g_hidden[b * HID + h] = fmaxf(acc, 0.0f);
}

// ---------------------------------------------------------------------------
// Kernel 3: wgen — per-sample weights, hi/lo bf16, global layout
// [b][oh][tap][split][c][o'] with o' chunk-swizzled: o' = ((ol>>3)^(c&3))*8+(ol&7)
// W2 column j = o*(CC*9) + c*9 + k.  grid (36, 4), 256 thr.
// ---------------------------------------------------------------------------
__global__ void wgen_kernel(const float* __restrict__ W2, const float* __restrict__ b2) {
    __shared__ float sh[8][HID];
    int b0 = blockIdx.y * 8;
    for (int i = threadIdx.x; i < 8 * HID; i += 256)
        sh[i >> 7][i & 127] = g_hidden[(b0 + (i >> 7)) * HID + (i & 127)];
    __syncthreads();

    int j0 = blockIdx.x * 1024 + threadIdx.x * 4;
    float4 acc[8];
#pragma unroll
    for (int bb = 0; bb < 8; ++bb) acc[bb] = make_float4(0.f, 0.f, 0.f, 0.f);

    for (int k = 0; k < HID; ++k) {
        float4 wv = *reinterpret_cast<const float4*>(&W2[(size_t)k * (OUTC * CC * 9) + j0]);
#pragma unroll
        for (int bb = 0; bb < 8; ++bb) {
            float hv = sh[bb][k];
            acc[bb].x = fmaf(hv, wv.x, acc[bb].x);
            acc[bb].y = fmaf(hv, wv.y, acc[bb].y);
            acc[bb].z = fmaf(hv, wv.z, acc[bb].z);
            acc[bb].w = fmaf(hv, wv.w, acc[bb].w);
        }
    }
    float4 bias = *reinterpret_cast<const float4*>(&b2[j0]);
#pragma unroll
    for (int bb = 0; bb < 8; ++bb) {
        float vals[4] = {acc[bb].x + bias.x, acc[bb].y + bias.y,
                         acc[bb].z + bias.z, acc[bb].w + bias.w};
#pragma unroll
        for (int q = 0; q < 4; ++q) {
            int j = j0 + q;
            int o = j / (CC * 9);
            int rem = j % (CC * 9);
            int c = rem / 9;
            int k = rem % 9;
            float v = vals[q];
            __nv_bfloat16 hi = __float2bfloat16(v);
            float remv = v - __bfloat162float(hi);
            __nv_bfloat16 lo = __float2bfloat16(remv);
            int oh = o >> 5, ol = o & 31;
            int op = (((ol >> 3) ^ (c & 3)) << 3) | (ol & 7);
            size_t base = ((((size_t)(b0 + bb) * 2 + oh) * 9 + k) * 2) * WTILE
                        + (size_t)c * 32 + op;
            g_wt[base]         = *reinterpret_cast<uint16_t*>(&hi);
            g_wt[base + WTILE] = *reinterpret_cast<uint16_t*>(&lo);
        }
    }
}

// ---------------------------------------------------------------------------
// Kernel 4: conv as implicit GEMM on mma.sync bf16 (3-split).
// grid (oh=2, htile=16, b=32), 256 threads (8 warps).
// Warp wid: w-tile [wid*16, +16).  All warps: 32 o (o-half), full K.
// Per h-row: D[16w x 32o] += sum over tap(dr,dc), c: A(x plane h-1+dr,
//   rows shifted by dc) @ B(weights tap).  Taps shift A row pointers only.
// ---------------------------------------------------------------------------
#define SM_W     128
#define SM_X     (128 + 73728)           // 73856
#define SLOT     (2 * PBYTES)            // 33280
#define SM_TOTAL (73856 + 4 * SLOT)      // 206976

__global__ __launch_bounds__(256, 1)
void conv_kernel(float* __restrict__ out) {
    extern __shared__ char smem[];
    uint32_t sb = smem_u32(smem);
    int b = blockIdx.z;
    int h0 = blockIdx.y * 8;
    int oh = blockIdx.x, o0 = oh * 32;
    int tid = threadIdx.x;
    int lane = tid & 31, wid = tid >> 5;

    if (tid == 0) {
        MBAR_INIT(sb, 1);
        asm volatile("fence.proxy.async.shared::cta;" ::: "memory");
    }
    __syncthreads();

    const uint16_t* xh = g_xhi + (size_t)b * HH * PSIZE;
    const uint16_t* xl = g_xlo + (size_t)b * HH * PSIZE;

    // prologue: weights + planes h0-1..h0+1
    if (tid == 0) {
        uint32_t bytes = 2 * WSLICE;
        for (int d = 0; d < 3; ++d) {
            int p = h0 - 1 + d;
            if (p >= 0 && p < HH) bytes += SLOT;
        }
        MBAR_EXPECT_TX(sb, bytes);
        BULK_G2S(sb + SM_W, g_wt + ((size_t)b * 2 + oh) * WSLICE, 2u * WSLICE, sb);
        for (int d = 0; d < 3; ++d) {
            int p = h0 - 1 + d;
            if (p < 0 || p >= HH) continue;
            uint32_t slot = (uint32_t)(p & 3) * SLOT;
            BULK_G2S(sb + SM_X + slot,          xh + (size_t)p * PSIZE, PBYTES, sb);
            BULK_G2S(sb + SM_X + slot + PBYTES, xl + (size_t)p * PSIZE, PBYTES, sb);
        }
    }

    int lph = 0;
    bool pending = true;
    int w0 = wid * 16;
    int r7 = lane & 7, half = (lane >> 3) & 1, quad = lane >> 4, l3 = lane & 3;
    int rbase = r7 + half * 8;

    for (int hh = 0; hh < 8; ++hh) {
        int h = h0 + hh;
        if (pending) { MBAR_WAIT(sb, lph); lph ^= 1; }
        __syncthreads();   // all warps done reading retiring ring slot

        pending = (hh < 7) && (h + 2 < HH);
        if (pending && tid == 0) {
            MBAR_EXPECT_TX(sb, (uint32_t)SLOT);
            int p = h + 2;
            uint32_t slot = (uint32_t)(p & 3) * SLOT;
            BULK_G2S(sb + SM_X + slot,          xh + (size_t)p * PSIZE, PBYTES, sb);
            BULK_G2S(sb + SM_X + slot + PBYTES, xl + (size_t)p * PSIZE, PBYTES, sb);
        }

        float acc[4][4];
#pragma unroll
        for (int nt = 0; nt < 4; ++nt)
#pragma unroll
            for (int q = 0; q < 4; ++q) acc[nt][q] = 0.f;

        for (int dr = 0; dr < 3; ++dr) {
            int p = h - 1 + dr;
            if ((unsigned)p >= (unsigned)HH) continue;
            uint32_t pb = sb + SM_X + (uint32_t)(p & 3) * SLOT;
#pragma unroll
            for (int dc = 0; dc < 3; ++dc) {
                uint32_t bt = sb + SM_W + (uint32_t)(dr * 3 + dc) * 8192u;
                int srow = w0 + dc + rbase;          // storage row (w+1 indexing)
                uint32_t abase = pb + (uint32_t)srow * 128u;
                int ax = srow & 7;
#pragma unroll
                for (int ks = 0; ks < 4; ++ks) {
                    uint32_t ah[4], al[4], bh[8], bl[8];
                    uint32_t aaddr = abase + (uint32_t)((((ks << 1) | quad) ^ ax) << 4);
                    ldm_x4(ah, aaddr);
                    ldm_x4(al, aaddr + PBYTES);
                    uint32_t brow = bt + (uint32_t)((ks * 16 + rbase) * 64);
                    uint32_t b0a = brow + (uint32_t)(((0 | quad) ^ l3) << 4);
                    uint32_t b1a = brow + (uint32_t)(((2 | quad) ^ l3) << 4);
                    ldm_x4_t(bh,     b0a);
                    ldm_x4_t(bh + 4, b1a);
                    ldm_x4_t(bl,     b0a + 4096u);
                    ldm_x4_t(bl + 4, b1a + 4096u);
#pragma unroll
                    for (int nt = 0; nt < 4; ++nt) {
                        mma_bf16(acc[nt], ah, bh + nt * 2);   // xh*wh
                        mma_bf16(acc[nt], al, bh + nt * 2);   // xl*wh
                        mma_bf16(acc[nt], ah, bl + nt * 2);   // xh*wl
                    }
                }
            }
        }

        // epilogue: D[m=w][n=o]; thread: m = lane>>2 (+8), n = l3*2 (+1)
        int wcol = w0 + (lane >> 2);
#pragma unroll
        for (int nt = 0; nt < 4; ++nt) {
            int o = o0 + nt * 8 + l3 * 2;
            float* p0 = out + (((size_t)b * OUTC + o) * HH + h) * WW + wcol;
            float* p1 = p0 + (size_t)HH * WW;
            p0[0] = acc[nt][0];
            p1[0] = acc[nt][1];
            p0[8] = acc[nt][2];
            p1[8] = acc[nt][3];
        }
    }
}

// ---------------------------------------------------------------------------
extern "C" void kernel_launch(void* const* d_in, const int* in_sizes, int n_in,
                              void* d_out, int out_size) {
    const float* x  = (const float*)d_in[0];
    const float* W1 = (const float*)d_in[1];
    const float* b1 = (const float*)d_in[2];
    const float* W2 = (const float*)d_in[3];
    const float* b2 = (const float*)d_in[4];
    float* out = (float*)d_out;

    cudaFuncSetAttribute(conv_kernel, cudaFuncAttributeMaxDynamicSharedMemorySize, SM_TOTAL);

    zero_stats_kernel<<<8, 256>>>();
    prep_kernel<<<dim3(HH, BB), 256>>>(x);
    hidden_kernel<<<BB, HID>>>(W1, b1);
    wgen_kernel<<<dim3(36, 4), 256>>>(W2, b2);
    conv_kernel<<<dim3(2, 16, BB), 256, SM_TOTAL>>>(out);
}

// round 7
// speedup vs baseline: 4.5385x; 1.4594x over previous
#include <cuda_runtime.h>
#include <cuda_fp16.h>
#include <cstdint>

#define BB   32
#define CC   64
#define HH   128
#define WW   128
#define OUTC 64
#define HID  128

// NHWC planes with halo rows: per (b,h): 130 rows (w=-1..128) x 64 c, fp16
#define PROW   64                 // elems per row (128B)
#define PSIZE  (130 * PROW)       // 8320 elems per plane per split
#define PBYTES (PSIZE * 2)        // 16640 B
// Weights per (b, o-half): [9 tap][64 c][32 o'] fp16 = 18432 elems
#define WTILE  (64 * 32)          // 2048 elems per tap
#define WSLICE (9 * WTILE)        // 18432

// ---------------------------------------------------------------------------
// Device scratch (static globals — no allocation allowed)
// ---------------------------------------------------------------------------
__device__ float g_stats[BB * CC];
__device__ float g_hidden[BB * HID];
__device__ __align__(128) uint16_t g_wt[(size_t)BB * 2 * WSLICE];
__device__ __align__(128) uint16_t g_xhi[(size_t)BB * HH * PSIZE];
__device__ __align__(128) uint16_t g_xlo[(size_t)BB * HH * PSIZE];

// ---------------------------------------------------------------------------
// PTX helpers
// ---------------------------------------------------------------------------
__device__ __forceinline__ uint32_t smem_u32(const void* p) {
    uint32_t a;
    asm("{ .reg .u64 t; cvta.to.shared.u64 t, %1; cvt.u32.u64 %0, t; }" : "=r"(a) : "l"(p));
    return a;
}
#define MBAR_INIT(a, n) asm volatile("mbarrier.init.shared.b64 [%0], %1;" :: "r"(a), "r"(n) : "memory")
#define MBAR_EXPECT_TX(a, b) asm volatile("mbarrier.arrive.expect_tx.shared.b64 _, [%0], %1;" :: "r"(a), "r"(b) : "memory")
#define MBAR_WAIT(a, ph) do {                                                         \
    uint32_t _m = (a), _p = (ph), _d;                                                 \
    asm volatile("{\n\t.reg .pred p;\n\t"                                             \
        "mbarrier.try_wait.parity.acquire.cta.shared::cta.b64 p, [%1], %2;\n\t"       \
        "selp.b32 %0, 1, 0, p;\n\t}" : "=r"(_d) : "r"(_m), "r"(_p) : "memory");       \
    if (!_d) {                                                                        \
        asm volatile("{\n\t.reg .pred P1;\n\t"                                        \
            "WL_%=:\n\t"                                                              \
            "mbarrier.try_wait.parity.acquire.cta.shared::cta.b64 P1, [%0], %1, 0x989680;\n\t" \
            "@P1 bra.uni WD_%=;\n\t"                                                  \
            "bra.uni WL_%=;\n\t"                                                      \
            "WD_%=:\n\t}" :: "r"(_m), "r"(_p) : "memory");                            \
    }                                                                                 \
} while (0)
#define BULK_G2S(dst, src, bytes, mbar)                                               \
    asm volatile("cp.async.bulk.shared::cta.global.mbarrier::complete_tx::bytes "      \
                 "[%0], [%1], %2, [%3];"                                               \
                 :: "r"(dst), "l"(src), "r"(bytes), "r"(mbar) : "memory")

__device__ __forceinline__ void ldm_x4(uint32_t* r, uint32_t addr) {
    asm volatile("ldmatrix.sync.aligned.m8n8.x4.shared.b16 {%0,%1,%2,%3}, [%4];"
                 : "=r"(r[0]), "=r"(r[1]), "=r"(r[2]), "=r"(r[3]) : "r"(addr));
}
__device__ __forceinline__ void ldm_x4_t(uint32_t* r, uint32_t addr) {
    asm volatile("ldmatrix.sync.aligned.m8n8.x4.trans.shared.b16 {%0,%1,%2,%3}, [%4];"
                 : "=r"(r[0]), "=r"(r[1]), "=r"(r[2]), "=r"(r[3]) : "r"(addr));
}
__device__ __forceinline__ void mma_f16(float* d, const uint32_t* a, const uint32_t* b) {
    asm volatile("mma.sync.aligned.m16n8k16.row.col.f32.f16.f16.f32 "
                 "{%0,%1,%2,%3}, {%4,%5,%6,%7}, {%8,%9}, {%0,%1,%2,%3};"
                 : "+f"(d[0]), "+f"(d[1]), "+f"(d[2]), "+f"(d[3])
                 : "r"(a[0]), "r"(a[1]), "r"(a[2]), "r"(a[3]), "r"(b[0]), "r"(b[1]));
}

// ---------------------------------------------------------------------------
__global__ void zero_stats_kernel() {
    g_stats[blockIdx.x * 256 + threadIdx.x] = 0.f;
}

// ---------------------------------------------------------------------------
// Kernel 1: prep — NCHW fp32 -> halo'd NHWC fp16 hi/lo (chunk-swizzled) + sums
// grid (h=128, b=32), 256 threads.
// ---------------------------------------------------------------------------
__global__ __launch_bounds__(256) void prep_kernel(const float* __restrict__ x) {
    int h = blockIdx.x, b = blockIdx.y;
    __shared__ float s[CC * 129];
    const float* xb = x + (size_t)b * CC * HH * WW + (size_t)h * WW;
    int t = threadIdx.x;
#pragma unroll
    for (int i = 0; i < 32; ++i) {
        int idx = i * 256 + t;
        int c = idx >> 7, w = idx & 127;
        s[c * 129 + w] = xb[(size_t)c * (HH * WW) + w];
    }
    __syncthreads();
    if (t < CC) {
        float sum = 0.f;
#pragma unroll 8
        for (int w = 0; w < WW; ++w) sum += s[t * 129 + w];
        atomicAdd(&g_stats[b * CC + t], sum);
    }
    int w = t >> 1, half = t & 1;
    __align__(16) uint16_t hbuf[32];
    __align__(16) uint16_t lbuf[32];
#pragma unroll
    for (int e = 0; e < 32; ++e) {
        float v = s[(half * 32 + e) * 129 + w];
        __half hi = __float2half_rn(v);
        float rem = v - __half2float(hi);
        __half lo = __float2half_rn(rem);
        hbuf[e] = *reinterpret_cast<uint16_t*>(&hi);
        lbuf[e] = *reinterpret_cast<uint16_t*>(&lo);
    }
    size_t rowbase = ((size_t)b * HH + h) * PSIZE + (size_t)(w + 1) * PROW;
    uint16_t* dh = g_xhi + rowbase;
    uint16_t* dl = g_xlo + rowbase;
    int ph = (w + 1) & 7;
#pragma unroll
    for (int g = 0; g < 4; ++g) {
        int chunk = (half * 4 + g) ^ ph;
        *reinterpret_cast<uint4*>(dh + chunk * 8) = *reinterpret_cast<const uint4*>(hbuf + g * 8);
        *reinterpret_cast<uint4*>(dl + chunk * 8) = *reinterpret_cast<const uint4*>(lbuf + g * 8);
    }
    if (t < 32) {
        int reg = t >> 3, ch = t & 7;
        uint16_t* base = ((reg & 2) ? g_xlo : g_xhi)
                       + ((size_t)b * HH + h) * PSIZE
                       + ((reg & 1) ? (size_t)129 * PROW : 0) + ch * 8;
        *reinterpret_cast<uint4*>(base) = make_uint4(0u, 0u, 0u, 0u);
    }
}

// ---------------------------------------------------------------------------
// Kernel 2: hidden = relu(mean @ W1 + b1)
// ---------------------------------------------------------------------------
__global__ void hidden_kernel(const float* __restrict__ W1, const float* __restrict__ b1) {
    int b = blockIdx.x;
    __shared__ float s[CC];
    if (threadIdx.x < CC) s[threadIdx.x] = g_stats[b * CC + threadIdx.x] * (1.0f / (HH * WW));
    __syncthreads();
    int h = threadIdx.x;
    float acc = b1[h];
#pragma unroll 8
    for (int c = 0; c < CC; ++c) acc += s[c] * W1[c * HID + h];
    g_hidden[b * HID + h] = fmaxf(acc, 0.0f);
}

// ---------------------------------------------------------------------------
// Kernel 3: wgen — per-sample weights -> single fp16, layout
// [b][oh][tap][c][o'] with o' chunk-swizzled: o' = ((ol>>3)^(c&3))*8+(ol&7)
// W2 column j = o*(CC*9) + c*9 + k.  grid (72, 4), 256 thr, 2 cols/thread.
// ---------------------------------------------------------------------------
__global__ __launch_bounds__(256) void wgen_kernel(const float* __restrict__ W2, const float* __restrict__ b2) {
    __shared__ float sh[8][HID];
    int b0 = blockIdx.y * 8;
    for (int i = threadIdx.x; i < 8 * HID; i += 256)
        sh[i >> 7][i & 127] = g_hidden[(b0 + (i >> 7)) * HID + (i & 127)];
    __syncthreads();

    int j0 = blockIdx.x * 512 + threadIdx.x * 2;
    float2 acc[8];
#pragma unroll
    for (int bb = 0; bb < 8; ++bb) acc[bb] = make_float2(0.f, 0.f);

#pragma unroll 4
    for (int k = 0; k < HID; ++k) {
        float2 wv = *reinterpret_cast<const float2*>(&W2[(size_t)k * (OUTC * CC * 9) + j0]);
#pragma unroll
        for (int bb = 0; bb < 8; ++bb) {
            float hv = sh[bb][k];
            acc[bb].x = fmaf(hv, wv.x, acc[bb].x);
            acc[bb].y = fmaf(hv, wv.y, acc[bb].y);
        }
    }
    float2 bias = *reinterpret_cast<const float2*>(&b2[j0]);
#pragma unroll
    for (int bb = 0; bb < 8; ++bb) {
        float vals[2] = {acc[bb].x + bias.x, acc[bb].y + bias.y};
#pragma unroll
        for (int q = 0; q < 2; ++q) {
            int j = j0 + q;
            int o = j / (CC * 9);
            int rem = j % (CC * 9);
            int c = rem / 9;
            int k = rem % 9;
            __half hv = __float2half_rn(vals[q]);
            int oh = o >> 5, ol = o & 31;
            int op = (((ol >> 3) ^ (c & 3)) << 3) | (ol & 7);
            size_t base = ((((size_t)(b0 + bb) * 2 + oh) * 9 + k) * 64 + c) * 32 + op;
            g_wt[base] = *reinterpret_cast<uint16_t*>(&hv);
        }
    }
}

// ---------------------------------------------------------------------------
// Kernel 4: conv as implicit GEMM on mma.sync fp16, 2-split (xh + xl) @ w.
// grid (oh=2, htile=16, b=32), 256 threads (8 warps).
// ---------------------------------------------------------------------------
#define SM_W     128
#define SM_X     (128 + 36864)           // 36992
#define SLOT     (2 * PBYTES)            // 33280
#define SM_TOTAL (36992 + 4 * SLOT)      // 170112

__global__ __launch_bounds__(256, 1)
void conv_kernel(float* __restrict__ out) {
    extern __shared__ char smem[];
    uint32_t sb = smem_u32(smem);
    int b = blockIdx.z;
    int h0 = blockIdx.y * 8;
    int oh = blockIdx.x, o0 = oh * 32;
    int tid = threadIdx.x;
    int lane = tid & 31, wid = tid >> 5;

    if (tid == 0) {
        MBAR_INIT(sb, 1);
        asm volatile("fence.proxy.async.shared::cta;" ::: "memory");
    }
    __syncthreads();

    const uint16_t* xh = g_xhi + (size_t)b * HH * PSIZE;
    const uint16_t* xl = g_xlo + (size_t)b * HH * PSIZE;

    // prologue: weights + planes h0-1..h0+1
    if (tid == 0) {
        uint32_t bytes = 2 * WSLICE;     // 36864 B
        for (int d = 0; d < 3; ++d) {
            int p = h0 - 1 + d;
            if (p >= 0 && p < HH) bytes += SLOT;
        }
        MBAR_EXPECT_TX(sb, bytes);
        BULK_G2S(sb + SM_W, g_wt + ((size_t)b * 2 + oh) * WSLICE, 2u * WSLICE, sb);
        for (int d = 0; d < 3; ++d) {
            int p = h0 - 1 + d;
            if (p < 0 || p >= HH) continue;
            uint32_t slot = (uint32_t)(p & 3) * SLOT;
            BULK_G2S(sb + SM_X + slot,          xh + (size_t)p * PSIZE, PBYTES, sb);
            BULK_G2S(sb + SM_X + slot + PBYTES, xl + (size_t)p * PSIZE, PBYTES, sb);
        }
    }

    int lph = 0;
    bool pending = true;
    int w0 = wid * 16;
    int r7 = lane & 7, half = (lane >> 3) & 1, quad = lane >> 4, l3 = lane & 3;
    int rbase = r7 + half * 8;

    for (int hh = 0; hh < 8; ++hh) {
        int h = h0 + hh;
        if (pending) { MBAR_WAIT(sb, lph); lph ^= 1; }
        __syncthreads();

        pending = (hh < 7) && (h + 2 < HH);
        if (pending && tid == 0) {
            MBAR_EXPECT_TX(sb, (uint32_t)SLOT);
            int p = h + 2;
            uint32_t slot = (uint32_t)(p & 3) * SLOT;
            BULK_G2S(sb + SM_X + slot,          xh + (size_t)p * PSIZE, PBYTES, sb);
            BULK_G2S(sb + SM_X + slot + PBYTES, xl + (size_t)p * PSIZE, PBYTES, sb);
        }

        float acc[4][4];
#pragma unroll
        for (int nt = 0; nt < 4; ++nt)
#pragma unroll
            for (int q = 0; q < 4; ++q) acc[nt][q] = 0.f;

        for (int dr = 0; dr < 3; ++dr) {
            int p = h - 1 + dr;
            if ((unsigned)p >= (unsigned)HH) continue;
            uint32_t pb = sb + SM_X + (uint32_t)(p & 3) * SLOT;
#pragma unroll
            for (int dc = 0; dc < 3; ++dc) {
                uint32_t bt = sb + SM_W + (uint32_t)(dr * 3 + dc) * 4096u;
                int srow = w0 + dc + rbase;
                uint32_t abase = pb + (uint32_t)srow * 128u;
                int ax = srow & 7;
#pragma unroll
                for (int ks = 0; ks < 4; ++ks) {
                    uint32_t ah[4], al[4], bh[8];
                    uint32_t aaddr = abase + (uint32_t)((((ks << 1) | quad) ^ ax) << 4);
                    ldm_x4(ah, aaddr);
                    ldm_x4(al, aaddr + PBYTES);
                    uint32_t brow = bt + (uint32_t)((ks * 16 + rbase) * 64);
                    ldm_x4_t(bh,     brow + (uint32_t)(((0 | quad) ^ l3) << 4));
                    ldm_x4_t(bh + 4, brow + (uint32_t)(((2 | quad) ^ l3) << 4));
#pragma unroll
                    for (int nt = 0; nt < 4; ++nt) {
                        mma_f16(acc[nt], ah, bh + nt * 2);   // xh * w
                        mma_f16(acc[nt], al, bh + nt * 2);   // xl * w
                    }
                }
            }
        }

        int wcol = w0 + (lane >> 2);
#pragma unroll
        for (int nt = 0; nt < 4; ++nt) {
            int o = o0 + nt * 8 + l3 * 2;
            float* p0 = out + (((size_t)b * OUTC + o) * HH + h) * WW + wcol;
            float* p1 = p0 + (size_t)HH * WW;
            p0[0] = acc[nt][0];
            p1[0] = acc[nt][1];
            p0[8] = acc[nt][2];
            p1[8] = acc[nt][3];
        }
    }
}

// ---------------------------------------------------------------------------
extern "C" void kernel_launch(void* const* d_in, const int* in_sizes, int n_in,
                              void* d_out, int out_size) {
    const float* x  = (const float*)d_in[0];
    const float* W1 = (const float*)d_in[1];
    const float* b1 = (const float*)d_in[2];
    const float* W2 = (const float*)d_in[3];
    const float* b2 = (const float*)d_in[4];
    float* out = (float*)d_out;

    cudaFuncSetAttribute(conv_kernel, cudaFuncAttributeMaxDynamicSharedMemorySize, SM_TOTAL);

    zero_stats_kernel<<<8, 256>>>();
    prep_kernel<<<dim3(HH, BB), 256>>>(x);
    hidden_kernel<<<BB, HID>>>(W1, b1);
    wgen_kernel<<<dim3(72, 4), 256>>>(W2, b2);
    conv_kernel<<<dim3(2, 16, BB), 256, SM_TOTAL>>>(out);
}

// round 8
// speedup vs baseline: 5.3894x; 1.1875x over previous
#include <cuda_runtime.h>
#include <cuda_fp16.h>
#include <cstdint>

#define BB   32
#define CC   64
#define HH   128
#define WW   128
#define OUTC 64
#define HID  128

// NHWC planes with halo rows: per (b,h): 130 rows (w=-1..128) x 64 c, fp16
#define PROW   64                 // elems per row (128B)
#define PSIZE  (130 * PROW)       // 8320 elems per plane
#define PBYTES (PSIZE * 2)        // 16640 B
// Weights per (b, o-half): [9 tap][64 c][32 o'] fp16 = 18432 elems
#define WTILE  (64 * 32)
#define WSLICE (9 * WTILE)        // 18432

// ---------------------------------------------------------------------------
// Device scratch (static globals — no allocation allowed)
// ---------------------------------------------------------------------------
__device__ float g_stats[BB * CC];
__device__ float g_hidden[BB * HID];
__device__ __align__(128) uint16_t g_wt[(size_t)BB * 2 * WSLICE];
__device__ __align__(128) uint16_t g_xhi[(size_t)BB * HH * PSIZE];

// ---------------------------------------------------------------------------
// PTX helpers
// ---------------------------------------------------------------------------
__device__ __forceinline__ uint32_t smem_u32(const void* p) {
    uint32_t a;
    asm("{ .reg .u64 t; cvta.to.shared.u64 t, %1; cvt.u32.u64 %0, t; }" : "=r"(a) : "l"(p));
    return a;
}
#define MBAR_INIT(a, n) asm volatile("mbarrier.init.shared.b64 [%0], %1;" :: "r"(a), "r"(n) : "memory")
#define MBAR_EXPECT_TX(a, b) asm volatile("mbarrier.arrive.expect_tx.shared.b64 _, [%0], %1;" :: "r"(a), "r"(b) : "memory")
#define MBAR_WAIT(a, ph) do {                                                         \
    uint32_t _m = (a), _p = (ph), _d;                                                 \
    asm volatile("{\n\t.reg .pred p;\n\t"                                             \
        "mbarrier.try_wait.parity.acquire.cta.shared::cta.b64 p, [%1], %2;\n\t"       \
        "selp.b32 %0, 1, 0, p;\n\t}" : "=r"(_d) : "r"(_m), "r"(_p) : "memory");       \
    if (!_d) {                                                                        \
        asm volatile("{\n\t.reg .pred P1;\n\t"                                        \
            "WL_%=:\n\t"                                                              \
            "mbarrier.try_wait.parity.acquire.cta.shared::cta.b64 P1, [%0], %1, 0x989680;\n\t" \
            "@P1 bra.uni WD_%=;\n\t"                                                  \
            "bra.uni WL_%=;\n\t"                                                      \
            "WD_%=:\n\t}" :: "r"(_m), "r"(_p) : "memory");                            \
    }                                                                                 \
} while (0)
#define BULK_G2S(dst, src, bytes, mbar)                                               \
    asm volatile("cp.async.bulk.shared::cta.global.mbarrier::complete_tx::bytes "      \
                 "[%0], [%1], %2, [%3];"                                               \
                 :: "r"(dst), "l"(src), "r"(bytes), "r"(mbar) : "memory")

__device__ __forceinline__ void ldm_x4(uint32_t* r, uint32_t addr) {
    asm volatile("ldmatrix.sync.aligned.m8n8.x4.shared.b16 {%0,%1,%2,%3}, [%4];"
                 : "=r"(r[0]), "=r"(r[1]), "=r"(r[2]), "=r"(r[3]) : "r"(addr));
}
__device__ __forceinline__ void ldm_x4_t(uint32_t* r, uint32_t addr) {
    asm volatile("ldmatrix.sync.aligned.m8n8.x4.trans.shared.b16 {%0,%1,%2,%3}, [%4];"
                 : "=r"(r[0]), "=r"(r[1]), "=r"(r[2]), "=r"(r[3]) : "r"(addr));
}
__device__ __forceinline__ void mma_f16(float* d, const uint32_t* a, const uint32_t* b) {
    asm volatile("mma.sync.aligned.m16n8k16.row.col.f32.f16.f16.f32 "
                 "{%0,%1,%2,%3}, {%4,%5,%6,%7}, {%8,%9}, {%0,%1,%2,%3};"
                 : "+f"(d[0]), "+f"(d[1]), "+f"(d[2]), "+f"(d[3])
                 : "r"(a[0]), "r"(a[1]), "r"(a[2]), "r"(a[3]), "r"(b[0]), "r"(b[1]));
}

// ---------------------------------------------------------------------------
__global__ void zero_stats_kernel() {
    g_stats[blockIdx.x * 256 + threadIdx.x] = 0.f;
}

// ---------------------------------------------------------------------------
// Kernel 1: prep — NCHW fp32 -> halo'd NHWC fp16 (chunk-swizzled) + sums
// grid (h=128, b=32), 256 threads.
// ---------------------------------------------------------------------------
__global__ __launch_bounds__(256) void prep_kernel(const float* __restrict__ x) {
    int h = blockIdx.x, b = blockIdx.y;
    __shared__ float s[CC * 129];
    const float* xb = x + (size_t)b * CC * HH * WW + (size_t)h * WW;
    int t = threadIdx.x;
#pragma unroll
    for (int i = 0; i < 32; ++i) {
        int idx = i * 256 + t;
        int c = idx >> 7, w = idx & 127;
        s[c * 129 + w] = xb[(size_t)c * (HH * WW) + w];
    }
    __syncthreads();
    if (t < CC) {
        float sum = 0.f;
#pragma unroll 8
        for (int w = 0; w < WW; ++w) sum += s[t * 129 + w];
        atomicAdd(&g_stats[b * CC + t], sum);
    }
    int w = t >> 1, half = t & 1;
    __align__(16) uint16_t hbuf[32];
#pragma unroll
    for (int e = 0; e < 32; ++e) {
        __half hv = __float2half_rn(s[(half * 32 + e) * 129 + w]);
        hbuf[e] = *reinterpret_cast<uint16_t*>(&hv);
    }
    size_t rowbase = ((size_t)b * HH + h) * PSIZE + (size_t)(w + 1) * PROW;
    uint16_t* dh = g_xhi + rowbase;
    int ph = (w + 1) & 7;
#pragma unroll
    for (int g = 0; g < 4; ++g) {
        int chunk = (half * 4 + g) ^ ph;
        *reinterpret_cast<uint4*>(dh + chunk * 8) = *reinterpret_cast<const uint4*>(hbuf + g * 8);
    }
    // zero halo rows 0 and 129: 2 regions x 8 chunks of 16B
    if (t < 16) {
        int reg = t >> 3, ch = t & 7;
        uint16_t* base = g_xhi + ((size_t)b * HH + h) * PSIZE
                       + (reg ? (size_t)129 * PROW : 0) + ch * 8;
        *reinterpret_cast<uint4*>(base) = make_uint4(0u, 0u, 0u, 0u);
    }
}

// ---------------------------------------------------------------------------
// Kernel 2: hidden = relu(mean @ W1 + b1)
// ---------------------------------------------------------------------------
__global__ void hidden_kernel(const float* __restrict__ W1, const float* __restrict__ b1) {
    int b = blockIdx.x;
    __shared__ float s[CC];
    if (threadIdx.x < CC) s[threadIdx.x] = g_stats[b * CC + threadIdx.x] * (1.0f / (HH * WW));
    __syncthreads();
    int h = threadIdx.x;
    float acc = b1[h];
#pragma unroll 8
    for (int c = 0; c < CC; ++c) acc += s[c] * W1[c * HID + h];
    g_hidden[b * HID + h] = fmaxf(acc, 0.0f);
}

// ---------------------------------------------------------------------------
// Kernel 3: wgen — per-sample weights -> fp16, layout [b][oh][tap][c][o']
// o' chunk-swizzled: o' = ((ol>>3)^(c&3))*8+(ol&7)
// W2 column j = o*(CC*9) + c*9 + k.  grid (72, 8), 256 thr, 2 cols x 4 b.
// ---------------------------------------------------------------------------
__global__ __launch_bounds__(256) void wgen_kernel(const float* __restrict__ W2, const float* __restrict__ b2) {
    __shared__ float sh[4][HID];
    int b0 = blockIdx.y * 4;
    for (int i = threadIdx.x; i < 4 * HID; i += 256)
        sh[i >> 7][i & 127] = g_hidden[(b0 + (i >> 7)) * HID + (i & 127)];
    __syncthreads();

    int j0 = blockIdx.x * 512 + threadIdx.x * 2;
    float2 acc[4];
#pragma unroll
    for (int bb = 0; bb < 4; ++bb) acc[bb] = make_float2(0.f, 0.f);

#pragma unroll 8
    for (int k = 0; k < HID; ++k) {
        float2 wv = *reinterpret_cast<const float2*>(&W2[(size_t)k * (OUTC * CC * 9) + j0]);
#pragma unroll
        for (int bb = 0; bb < 4; ++bb) {
            float hv = sh[bb][k];
            acc[bb].x = fmaf(hv, wv.x, acc[bb].x);
            acc[bb].y = fmaf(hv, wv.y, acc[bb].y);
        }
    }
    float2 bias = *reinterpret_cast<const float2*>(&b2[j0]);
#pragma unroll
    for (int bb = 0; bb < 4; ++bb) {
        float vals[2] = {acc[bb].x + bias.x, acc[bb].y + bias.y};
#pragma unroll
        for (int q = 0; q < 2; ++q) {
            int j = j0 + q;
            int o = j / (CC * 9);
            int rem = j % (CC * 9);
            int c = rem / 9;
            int k = rem % 9;
            __half hv = __float2half_rn(vals[q]);
            int oh = o >> 5, ol = o & 31;
            int op = (((ol >> 3) ^ (c & 3)) << 3) | (ol & 7);
            size_t base = ((((size_t)(b0 + bb) * 2 + oh) * 9 + k) * 64 + c) * 32 + op;
            g_wt[base] = *reinterpret_cast<uint16_t*>(&hv);
        }
    }
}

// ---------------------------------------------------------------------------
// Kernel 4: conv as implicit GEMM on mma.sync fp16, single pass.
// grid (oh=2, htile=16, b=32), 256 threads (8 warps), 2 CTAs/SM.
// ---------------------------------------------------------------------------
#define SM_W     128
#define SM_X     (128 + 36864)           // 36992
#define SLOT     PBYTES                  // 16640
#define SM_TOTAL (36992 + 4 * SLOT)      // 103552

__global__ __launch_bounds__(256, 2)
void conv_kernel(float* __restrict__ out) {
    extern __shared__ char smem[];
    uint32_t sb = smem_u32(smem);
    int b = blockIdx.z;
    int h0 = blockIdx.y * 8;
    int oh = blockIdx.x, o0 = oh * 32;
    int tid = threadIdx.x;
    int lane = tid & 31, wid = tid >> 5;

    if (tid == 0) {
        MBAR_INIT(sb, 1);
        asm volatile("fence.proxy.async.shared::cta;" ::: "memory");
    }
    __syncthreads();

    const uint16_t* xh = g_xhi + (size_t)b * HH * PSIZE;

    // prologue: weights + planes h0-1..h0+1
    if (tid == 0) {
        uint32_t bytes = 2 * WSLICE;     // 36864 B (fp16 elems * 2)
        for (int d = 0; d < 3; ++d) {
            int p = h0 - 1 + d;
            if (p >= 0 && p < HH) bytes += SLOT;
        }
        MBAR_EXPECT_TX(sb, bytes);
        BULK_G2S(sb + SM_W, g_wt + ((size_t)b * 2 + oh) * WSLICE, 2u * WSLICE, sb);
        for (int d = 0; d < 3; ++d) {
            int p = h0 - 1 + d;
            if (p < 0 || p >= HH) continue;
            BULK_G2S(sb + SM_X + (uint32_t)(p & 3) * SLOT, xh + (size_t)p * PSIZE, PBYTES, sb);
        }
    }

    int lph = 0;
    bool pending = true;
    int w0 = wid * 16;
    int r7 = lane & 7, half = (lane >> 3) & 1, quad = lane >> 4, l3 = lane & 3;
    int rbase = r7 + half * 8;

    for (int hh = 0; hh < 8; ++hh) {
        int h = h0 + hh;
        if (pending) { MBAR_WAIT(sb, lph); lph ^= 1; }
        __syncthreads();

        pending = (hh < 7) && (h + 2 < HH);
        if (pending && tid == 0) {
            MBAR_EXPECT_TX(sb, (uint32_t)SLOT);
            int p = h + 2;
            BULK_G2S(sb + SM_X + (uint32_t)(p & 3) * SLOT, xh + (size_t)p * PSIZE, PBYTES, sb);
        }

        float acc[4][4];
#pragma unroll
        for (int nt = 0; nt < 4; ++nt)
#pragma unroll
            for (int q = 0; q < 4; ++q) acc[nt][q] = 0.f;

        for (int dr = 0; dr < 3; ++dr) {
            int p = h - 1 + dr;
            if ((unsigned)p >= (unsigned)HH) continue;
            uint32_t pb = sb + SM_X + (uint32_t)(p & 3) * SLOT;
#pragma unroll
            for (int dc = 0; dc < 3; ++dc) {
                uint32_t bt = sb + SM_W + (uint32_t)(dr * 3 + dc) * 4096u;
                int srow = w0 + dc + rbase;
                uint32_t abase = pb + (uint32_t)srow * 128u;
                int ax = srow & 7;
#pragma unroll
                for (int ks = 0; ks < 4; ++ks) {
                    uint32_t ah[4], bh[8];
                    ldm_x4(ah, abase + (uint32_t)((((ks << 1) | quad) ^ ax) << 4));
                    uint32_t brow = bt + (uint32_t)((ks * 16 + rbase) * 64);
                    ldm_x4_t(bh,     brow + (uint32_t)(((0 | quad) ^ l3) << 4));
                    ldm_x4_t(bh + 4, brow + (uint32_t)(((2 | quad) ^ l3) << 4));
#pragma unroll
                    for (int nt = 0; nt < 4; ++nt)
                        mma_f16(acc[nt], ah, bh + nt * 2);
                }
            }
        }

        int wcol = w0 + (lane >> 2);
#pragma unroll
        for (int nt = 0; nt < 4; ++nt) {
            int o = o0 + nt * 8 + l3 * 2;
            float* p0 = out + (((size_t)b * OUTC + o) * HH + h) * WW + wcol;
            float* p1 = p0 + (size_t)HH * WW;
            p0[0] = acc[nt][0];
            p1[0] = acc[nt][1];
            p0[8] = acc[nt][2];
            p1[8] = acc[nt][3];
        }
    }
}

// ---------------------------------------------------------------------------
extern "C" void kernel_launch(void* const* d_in, const int* in_sizes, int n_in,
                              void* d_out, int out_size) {
    const float* x  = (const float*)d_in[0];
    const float* W1 = (const float*)d_in[1];
    const float* b1 = (const float*)d_in[2];
    const float* W2 = (const float*)d_in[3];
    const float* b2 = (const float*)d_in[4];
    float* out = (float*)d_out;

    cudaFuncSetAttribute(conv_kernel, cudaFuncAttributeMaxDynamicSharedMemorySize, SM_TOTAL);

    zero_stats_kernel<<<8, 256>>>();
    prep_kernel<<<dim3(HH, BB), 256>>>(x);
    hidden_kernel<<<BB, HID>>>(W1, b1);
    wgen_kernel<<<dim3(72, 8), 256>>>(W2, b2);
    conv_kernel<<<dim3(2, 16, BB), 256, SM_TOTAL>>>(out);
}